// round 15
// baseline (speedup 1.0000x reference)
#include <cuda_runtime.h>
#include <cuda_fp16.h>
#include <math.h>
#include <stdint.h>

// ---------------------------------------------------------------------------
// MultiHeadSelfAttention, B=2, S=2048, D=2048, H=16, HD=128
//
//   attn_i = ( sum_{j<i} v_j + exp(s_ii) * v_i ) / Z_i
//   Z_i    = i + sum_{r>=i} exp( (q_i . k_r) / sqrt(D) )
//
// Round 14: critical-path surgery. QKV GEMM split into QK (batched, s0)
// and V (s2). V-GEMM + scan-prep run CONCURRENTLY with z_mma: path becomes
// conv + QK + max(z, V-chain) + scan + O instead of conv + QKV + z + ...
// ---------------------------------------------------------------------------

#define BB 2
#define SS 2048
#define DD 2048
#define HH 16
#define HDIM 128
#define NTOK (BB * SS)         // 4096
#define NCH 16
#define RS2 144                // gemm smem row stride (128B data + 16B pad)
#define STG (128 * RS2)        // one tile = 18432 B
#define GSM2 (4 * STG)         // 2 stages x (A + B) = 73728 B
#define ZRS 272                // z smem row stride (256B data + 16B pad)

// fp32 scratch
__device__ float g_Z[BB * HH * SS];
__device__ float g_E[BB * HH * SS];
__device__ float g_cs[BB * HH * NCH * HDIM];

// fp16 scratch
__device__ __half g_xh[(size_t)NTOK * DD];
__device__ __half g_qh[(size_t)NTOK * DD];
__device__ __half g_kh[(size_t)NTOK * DD];
__device__ __half g_vh[(size_t)NTOK * DD];
__device__ __half g_ah[(size_t)NTOK * DD];
__device__ __half g_wqh[(size_t)DD * DD];
__device__ __half g_wkh[(size_t)DD * DD];
__device__ __half g_wvh[(size_t)DD * DD];
__device__ __half g_woh[(size_t)DD * DD];

// ---------------------------------------------------------------------------
// Helpers (base compute_103 ISA only)
// ---------------------------------------------------------------------------
__device__ __forceinline__ uint32_t smem_u32(const void* p) {
    return (uint32_t)__cvta_generic_to_shared(p);
}

__device__ __forceinline__ void cp16(uint32_t dst, const void* src) {
    asm volatile("cp.async.cg.shared.global [%0], [%1], 16;" :: "r"(dst), "l"(src));
}

__device__ __forceinline__ void ldsm4(uint32_t& r0, uint32_t& r1, uint32_t& r2,
                                      uint32_t& r3, uint32_t addr) {
    asm volatile("ldmatrix.sync.aligned.m8n8.x4.shared.b16 {%0,%1,%2,%3}, [%4];"
                 : "=r"(r0), "=r"(r1), "=r"(r2), "=r"(r3) : "r"(addr));
}

__device__ __forceinline__ void mma_f16(float* c, const uint32_t* a,
                                        uint32_t b0, uint32_t b1) {
    asm volatile("mma.sync.aligned.m16n8k16.row.col.f32.f16.f16.f32 "
                 "{%0,%1,%2,%3}, {%4,%5,%6,%7}, {%8,%9}, {%0,%1,%2,%3};"
                 : "+f"(c[0]), "+f"(c[1]), "+f"(c[2]), "+f"(c[3])
                 : "r"(a[0]), "r"(a[1]), "r"(a[2]), "r"(a[3]), "r"(b0), "r"(b1));
}

// ---------------------------------------------------------------------------
// fp32 -> fp16 conversions
// ---------------------------------------------------------------------------
__global__ __launch_bounds__(256) void tofp16_kernel(
    const float* __restrict__ in, __half* __restrict__ out, int n)
{
    int i = (blockIdx.x * 256 + threadIdx.x) * 4;
    if (i >= n) return;
    float4 v = *(const float4*)(in + i);
    __half2* op = reinterpret_cast<__half2*>(out + i);
    op[0] = __floats2half2_rn(v.x, v.y);
    op[1] = __floats2half2_rn(v.z, v.w);
}

__global__ __launch_bounds__(256) void tofp16x3_kernel(
    const float* __restrict__ in0, __half* __restrict__ out0,
    const float* __restrict__ in1, __half* __restrict__ out1,
    const float* __restrict__ in2, __half* __restrict__ out2, int n)
{
    const float* in = (blockIdx.y == 0) ? in0 : (blockIdx.y == 1) ? in1 : in2;
    __half* out     = (blockIdx.y == 0) ? out0 : (blockIdx.y == 1) ? out1 : out2;
    int i = (blockIdx.x * 256 + threadIdx.x) * 4;
    if (i >= n) return;
    float4 v = *(const float4*)(in + i);
    __half2* op = reinterpret_cast<__half2*>(out + i);
    op[0] = __floats2half2_rn(v.x, v.y);
    op[1] = __floats2half2_rn(v.z, v.w);
}

// ---------------------------------------------------------------------------
// Shared GEMM core: acc += A[128xK] * B[128xK]^T over 32 BK=64 chunks.
// CTA tile 128x128, 128 threads (4 warps as 2x2), warp tile 64x64.
// ---------------------------------------------------------------------------
__device__ __forceinline__ void gemm_load_chunk(
    const __half* __restrict__ A, const __half* __restrict__ B,
    int bm, int bn, int k0, unsigned char* sA, unsigned char* sB, int tid)
{
#pragma unroll
    for (int l = 0; l < 8; l++) {
        int i = tid + l * 128;          // 1024 x 16B per tile
        int r = i >> 3;
        int seg = i & 7;
        cp16(smem_u32(sA + r * RS2 + seg * 16),
             A + (size_t)(bm + r) * DD + k0 + seg * 8);
        cp16(smem_u32(sB + r * RS2 + seg * 16),
             B + (size_t)(bn + r) * DD + k0 + seg * 8);
    }
    asm volatile("cp.async.commit_group;" ::: "memory");
}

__device__ __forceinline__ void gemm_core(
    const __half* __restrict__ A, const __half* __restrict__ B,
    int bm, int bn, int tid, unsigned char* gsm, float acc[4][8][4])
{
    unsigned char* sA[2] = { gsm, gsm + 2 * STG };
    unsigned char* sB[2] = { gsm + STG, gsm + 3 * STG };
    const int lid = tid & 31;
    const int wid = tid >> 5;
    const int wm = wid >> 1;
    const int wn = wid & 1;
    const int nch = 32;

    const int rowsel = (lid & 7) + ((lid >> 3) & 1) * 8;
    const int kbsel = (lid >> 4) * 16;

    gemm_load_chunk(A, B, bm, bn, 0, sA[0], sB[0], tid);

    for (int c = 0; c < nch; c++) {
        if (c + 1 < nch) {
            gemm_load_chunk(A, B, bm, bn, (c + 1) << 6,
                            sA[(c + 1) & 1], sB[(c + 1) & 1], tid);
            asm volatile("cp.async.wait_group 1;" ::: "memory");
        } else {
            asm volatile("cp.async.wait_group 0;" ::: "memory");
        }
        __syncthreads();

        const int buf = c & 1;
        uint32_t aBase = smem_u32(sA[buf]) + (wm * 64 + rowsel) * RS2 + kbsel;
        uint32_t bBase = smem_u32(sB[buf]) + (wn * 64 + rowsel) * RS2 + kbsel;

#pragma unroll
        for (int ks = 0; ks < 4; ks++) {
            uint32_t a[4][4];
#pragma unroll
            for (int mf = 0; mf < 4; mf++)
                ldsm4(a[mf][0], a[mf][1], a[mf][2], a[mf][3],
                      aBase + mf * 16 * RS2 + ks * 32);
#pragma unroll
            for (int ng = 0; ng < 4; ng++) {
                uint32_t r0, r1, r2, r3;
                ldsm4(r0, r1, r2, r3, bBase + ng * 16 * RS2 + ks * 32);
#pragma unroll
                for (int mf = 0; mf < 4; mf++) {
                    mma_f16(acc[mf][2 * ng + 0], a[mf], r0, r2);
                    mma_f16(acc[mf][2 * ng + 1], a[mf], r1, r3);
                }
            }
        }
        __syncthreads();
    }
}

// Batched QK: grid.z selects weight/bias/output (fp16 out).
__global__ __launch_bounds__(128) void gemm_qk(
    const __half* __restrict__ A,
    const __half* __restrict__ Bq, const __half* __restrict__ Bk,
    const float* __restrict__ biasq, const float* __restrict__ biask,
    __half* __restrict__ Cq, __half* __restrict__ Ck)
{
    extern __shared__ __align__(16) unsigned char gsm[];
    const int z = blockIdx.z;
    const __half* B = (z == 0) ? Bq : Bk;
    const float* bias = (z == 0) ? biasq : biask;
    __half* Ch = (z == 0) ? Cq : Ck;

    const int tid = threadIdx.x;
    const int lid = tid & 31;
    const int wid = tid >> 5;
    const int wm = wid >> 1, wn = wid & 1;
    const int bn = blockIdx.x * 128;
    const int bm = blockIdx.y * 128;

    float acc[4][8][4];
#pragma unroll
    for (int i = 0; i < 4; i++)
#pragma unroll
        for (int j = 0; j < 8; j++)
#pragma unroll
            for (int q = 0; q < 4; q++) acc[i][j][q] = 0.0f;

    gemm_core(A, B, bm, bn, tid, gsm, acc);

    const int trow = lid >> 2;
    const int tcol = (lid & 3) * 2;
#pragma unroll
    for (int mf = 0; mf < 4; mf++) {
        int r0 = bm + wm * 64 + mf * 16 + trow;
#pragma unroll
        for (int nt = 0; nt < 8; nt++) {
            int cc = bn + wn * 64 + nt * 8 + tcol;
            float2 bv = *(const float2*)(bias + cc);
            *(__half2*)(Ch + (size_t)r0 * DD + cc) =
                __floats2half2_rn(acc[mf][nt][0] + bv.x, acc[mf][nt][1] + bv.y);
            *(__half2*)(Ch + (size_t)(r0 + 8) * DD + cc) =
                __floats2half2_rn(acc[mf][nt][2] + bv.x, acc[mf][nt][3] + bv.y);
        }
    }
}

// Single GEMM, fp16 output (V projection).
__global__ __launch_bounds__(128) void gemm_h(
    const __half* __restrict__ A, const __half* __restrict__ B,
    const float* __restrict__ bias, __half* __restrict__ Ch)
{
    extern __shared__ __align__(16) unsigned char gsm[];
    const int tid = threadIdx.x;
    const int lid = tid & 31;
    const int wid = tid >> 5;
    const int wm = wid >> 1, wn = wid & 1;
    const int bn = blockIdx.x * 128;
    const int bm = blockIdx.y * 128;

    float acc[4][8][4];
#pragma unroll
    for (int i = 0; i < 4; i++)
#pragma unroll
        for (int j = 0; j < 8; j++)
#pragma unroll
            for (int q = 0; q < 4; q++) acc[i][j][q] = 0.0f;

    gemm_core(A, B, bm, bn, tid, gsm, acc);

    const int trow = lid >> 2;
    const int tcol = (lid & 3) * 2;
#pragma unroll
    for (int mf = 0; mf < 4; mf++) {
        int r0 = bm + wm * 64 + mf * 16 + trow;
#pragma unroll
        for (int nt = 0; nt < 8; nt++) {
            int cc = bn + wn * 64 + nt * 8 + tcol;
            float2 bv = *(const float2*)(bias + cc);
            *(__half2*)(Ch + (size_t)r0 * DD + cc) =
                __floats2half2_rn(acc[mf][nt][0] + bv.x, acc[mf][nt][1] + bv.y);
            *(__half2*)(Ch + (size_t)(r0 + 8) * DD + cc) =
                __floats2half2_rn(acc[mf][nt][2] + bv.x, acc[mf][nt][3] + bv.y);
        }
    }
}

// O projection: fp32 output.
__global__ __launch_bounds__(128) void gemm_o(
    const __half* __restrict__ A, const __half* __restrict__ B,
    const float* __restrict__ bias, float* __restrict__ C)
{
    extern __shared__ __align__(16) unsigned char gsm[];
    const int tid = threadIdx.x;
    const int lid = tid & 31;
    const int wid = tid >> 5;
    const int wm = wid >> 1, wn = wid & 1;
    const int bn = blockIdx.x * 128;
    const int bm = blockIdx.y * 128;

    float acc[4][8][4];
#pragma unroll
    for (int i = 0; i < 4; i++)
#pragma unroll
        for (int j = 0; j < 8; j++)
#pragma unroll
            for (int q = 0; q < 4; q++) acc[i][j][q] = 0.0f;

    gemm_core(A, B, bm, bn, tid, gsm, acc);

    const int trow = lid >> 2;
    const int tcol = (lid & 3) * 2;
#pragma unroll
    for (int mf = 0; mf < 4; mf++) {
        int r0 = bm + wm * 64 + mf * 16 + trow;
#pragma unroll
        for (int nt = 0; nt < 8; nt++) {
            int cc = bn + wn * 64 + nt * 8 + tcol;
            float2 bv = *(const float2*)(bias + cc);
            *(float2*)(C + (size_t)r0 * DD + cc) =
                make_float2(acc[mf][nt][0] + bv.x, acc[mf][nt][1] + bv.y);
            *(float2*)(C + (size_t)(r0 + 8) * DD + cc) =
                make_float2(acc[mf][nt][2] + bv.x, acc[mf][nt][3] + bv.y);
        }
    }
}

// ---------------------------------------------------------------------------
// z_mma: fp16 HMMA Z row-sums, reflected-pair balanced.
// Grid: (8, BB*HH). CTA bx handles i-tiles bx and 15-bx => uniform 34 chunks.
// ---------------------------------------------------------------------------
#define ZSMEM (128 * ZRS + 2 * 64 * ZRS)   // 69632

__global__ __launch_bounds__(256) void z_mma(
    const __half* __restrict__ Qh, const __half* __restrict__ Kh)
{
    extern __shared__ __align__(16) unsigned char zsm[];
    unsigned char* Qs = zsm;                    // 128 x 272B
    unsigned char* Ks[2] = { zsm + 128 * ZRS, zsm + 128 * ZRS + 64 * ZRS };

    const int tid = threadIdx.x;
    const int lid = tid & 31;
    const int w = tid >> 5;
    const int bh = blockIdx.y;
    const int b = bh >> 4;
    const int h = bh & 15;
    const float scale = 0.022097086912079612f;   // 1/sqrt(2048)

    const __half* Kg = Kh + (size_t)b * SS * DD + h * HDIM;
    float* Ep = g_E + (size_t)bh * SS;

    const int rowsel = (lid & 7) + ((lid >> 3) & 1) * 8;
    const int kbsel = (lid >> 4) * 16;

#pragma unroll 1
    for (int half = 0; half < 2; half++) {
        const int tile = (half == 0) ? (int)blockIdx.x : (15 - (int)blockIdx.x);
        const int i0 = tile * 128;
        const __half* Qg = Qh + ((size_t)b * SS + i0) * DD + h * HDIM;

        for (int i = tid; i < 128 * 16; i += 256) {
            int r = i >> 4, seg = i & 15;
            cp16(smem_u32(Qs + r * ZRS + seg * 16), Qg + (size_t)r * DD + seg * 8);
        }
        asm volatile("cp.async.commit_group;" ::: "memory");

        for (int i = tid; i < 64 * 16; i += 256) {
            int r = i >> 4, seg = i & 15;
            cp16(smem_u32(Ks[0] + r * ZRS + seg * 16),
                 Kg + (size_t)(i0 + r) * DD + seg * 8);
        }
        asm volatile("cp.async.commit_group;" ::: "memory");
        asm volatile("cp.async.wait_group 0;" ::: "memory");
        __syncthreads();

        uint32_t afr[8][4];
        {
            uint32_t aAddr = smem_u32(Qs) + (w * 16 + rowsel) * ZRS + kbsel;
#pragma unroll
            for (int ks = 0; ks < 8; ks++)
                ldsm4(afr[ks][0], afr[ks][1], afr[ks][2], afr[ks][3],
                      aAddr + ks * 32);
        }

        const int gi0 = i0 + w * 16 + (lid >> 2);    // rows gi0 and gi0+8
        float z0 = 0.0f, z1 = 0.0f;

        const int nch = (SS - i0) >> 6;
        for (int c = 0; c < nch; c++) {
            if (c + 1 < nch) {
                int r1 = i0 + (c + 1) * 64;
                unsigned char* kb = Ks[(c + 1) & 1];
                for (int i = tid; i < 64 * 16; i += 256) {
                    int r = i >> 4, seg = i & 15;
                    cp16(smem_u32(kb + r * ZRS + seg * 16),
                         Kg + (size_t)(r1 + r) * DD + seg * 8);
                }
                asm volatile("cp.async.commit_group;" ::: "memory");
                asm volatile("cp.async.wait_group 1;" ::: "memory");
            } else {
                asm volatile("cp.async.wait_group 0;" ::: "memory");
            }
            __syncthreads();

            const int r0 = i0 + c * 64;
            if (r0 + 64 > i0 + w * 16) {
                float sacc[8][4];
#pragma unroll
                for (int nt = 0; nt < 8; nt++)
#pragma unroll
                    for (int q = 0; q < 4; q++) sacc[nt][q] = 0.0f;

                uint32_t bAddr = smem_u32(Ks[c & 1]) + rowsel * ZRS + kbsel;
#pragma unroll
                for (int ks = 0; ks < 8; ks++) {
#pragma unroll
                    for (int ng = 0; ng < 4; ng++) {
                        uint32_t r0r, r1r, r2r, r3r;
                        ldsm4(r0r, r1r, r2r, r3r, bAddr + ng * 16 * ZRS + ks * 32);
                        mma_f16(sacc[2 * ng + 0], afr[ks], r0r, r2r);
                        mma_f16(sacc[2 * ng + 1], afr[ks], r1r, r3r);
                    }
                }

                const bool needmask = (r0 < i0 + w * 16 + 16);
                const int grb = r0 + 2 * (lid & 3);
#pragma unroll
                for (int nt = 0; nt < 8; nt++) {
                    int gr = grb + nt * 8;
                    if (!needmask) {
                        z0 += __expf(sacc[nt][0] * scale) + __expf(sacc[nt][1] * scale);
                        z1 += __expf(sacc[nt][2] * scale) + __expf(sacc[nt][3] * scale);
                    } else {
                        if (gr >= gi0) {
                            float e = __expf(sacc[nt][0] * scale);
                            z0 += e;
                            if (gr == gi0) Ep[gi0] = e;
                        }
                        if (gr + 1 >= gi0) {
                            float e = __expf(sacc[nt][1] * scale);
                            z0 += e;
                            if (gr + 1 == gi0) Ep[gi0] = e;
                        }
                        if (gr >= gi0 + 8) {
                            float e = __expf(sacc[nt][2] * scale);
                            z1 += e;
                            if (gr == gi0 + 8) Ep[gi0 + 8] = e;
                        }
                        if (gr + 1 >= gi0 + 8) {
                            float e = __expf(sacc[nt][3] * scale);
                            z1 += e;
                            if (gr + 1 == gi0 + 8) Ep[gi0 + 8] = e;
                        }
                    }
                }
            }
            __syncthreads();
        }

        z0 += __shfl_xor_sync(0xffffffffu, z0, 1);
        z0 += __shfl_xor_sync(0xffffffffu, z0, 2);
        z1 += __shfl_xor_sync(0xffffffffu, z1, 1);
        z1 += __shfl_xor_sync(0xffffffffu, z1, 2);
        if ((lid & 3) == 0) {
            g_Z[(size_t)bh * SS + gi0] = (float)gi0 + z0;
            g_Z[(size_t)bh * SS + gi0 + 8] = (float)(gi0 + 8) + z1;
        }
        __syncthreads();   // smem reuse across tiles
    }
}

// ---------------------------------------------------------------------------
// Prefix-sum of V (fp16) + apply -> fp16 attn
// ---------------------------------------------------------------------------
__global__ void vchunk_kernel(const __half* __restrict__ V)
{
    const int bh = blockIdx.x, ch = blockIdx.y, d = threadIdx.x;
    const int b = bh >> 4, h = bh & 15;
    const __half* vp = V + ((size_t)b * SS + ch * 128) * DD + h * HDIM + d;
    float sum = 0.0f;
#pragma unroll 8
    for (int i = 0; i < 128; i++) sum += __half2float(vp[(size_t)i * DD]);
    g_cs[((size_t)bh * NCH + ch) * HDIM + d] = sum;
}

__global__ void vprefix_kernel()
{
    const int bh = blockIdx.x, d = threadIdx.x;
    float run = 0.0f;
    for (int ch = 0; ch < NCH; ch++) {
        size_t idx = ((size_t)bh * NCH + ch) * HDIM + d;
        float t = g_cs[idx];
        g_cs[idx] = run;
        run += t;
    }
}

__global__ void scan_apply_kernel(const __half* __restrict__ V,
                                  __half* __restrict__ Ah)
{
    const int bh = blockIdx.x, ch = blockIdx.y, d = threadIdx.x;
    const int b = bh >> 4, h = bh & 15;
    float run = g_cs[((size_t)bh * NCH + ch) * HDIM + d];
    const size_t base = ((size_t)b * SS + ch * 128) * DD + h * HDIM + d;
    const __half* vp = V + base;
    const float* Ep = g_E + (size_t)bh * SS + ch * 128;
    const float* Zp = g_Z + (size_t)bh * SS + ch * 128;
#pragma unroll 4
    for (int i = 0; i < 128; i++) {
        float vv = __half2float(vp[(size_t)i * DD]);
        float rcp = __fdividef(1.0f, Zp[i]);
        Ah[base + (size_t)i * DD] = __float2half_rn((run + Ep[i] * vv) * rcp);
        run += vv;
    }
}

// ---------------------------------------------------------------------------
// Launch: QK on s0 -> { z_mma on s0 } || { V-GEMM + scan prep on s2 }
// ---------------------------------------------------------------------------
extern "C" void kernel_launch(void* const* d_in, const int* in_sizes, int n_in,
                              void* d_out, int out_size)
{
    const float* x   = (const float*)d_in[0];
    const float* wq  = (const float*)d_in[1];
    const float* bq  = (const float*)d_in[2];
    const float* wk  = (const float*)d_in[3];
    const float* bk  = (const float*)d_in[4];
    const float* wv  = (const float*)d_in[5];
    const float* bv  = (const float*)d_in[6];
    const float* wo  = (const float*)d_in[7];
    const float* bo  = (const float*)d_in[8];
    float* out = (float*)d_out;

    void *pqh, *pkh, *pvh, *pxh, *pah, *pwqh, *pwkh, *pwvh, *pwoh;
    cudaGetSymbolAddress(&pqh, g_qh);
    cudaGetSymbolAddress(&pkh, g_kh);
    cudaGetSymbolAddress(&pvh, g_vh);
    cudaGetSymbolAddress(&pxh, g_xh);
    cudaGetSymbolAddress(&pah, g_ah);
    cudaGetSymbolAddress(&pwqh, g_wqh);
    cudaGetSymbolAddress(&pwkh, g_wkh);
    cudaGetSymbolAddress(&pwvh, g_wvh);
    cudaGetSymbolAddress(&pwoh, g_woh);

    __half* qh = (__half*)pqh;
    __half* kh = (__half*)pkh;
    __half* vh = (__half*)pvh;
    __half* xh = (__half*)pxh;
    __half* ah = (__half*)pah;
    __half* wqh = (__half*)pwqh;
    __half* wkh = (__half*)pwkh;
    __half* wvh = (__half*)pwvh;
    __half* woh = (__half*)pwoh;

    cudaFuncSetAttribute(gemm_qk, cudaFuncAttributeMaxDynamicSharedMemorySize, GSM2);
    cudaFuncSetAttribute(gemm_h, cudaFuncAttributeMaxDynamicSharedMemorySize, GSM2);
    cudaFuncSetAttribute(gemm_o, cudaFuncAttributeMaxDynamicSharedMemorySize, GSM2);
    cudaFuncSetAttribute(z_mma, cudaFuncAttributeMaxDynamicSharedMemorySize, ZSMEM);

    static cudaStream_t s2 = []() {
        cudaStream_t s; cudaStreamCreateWithFlags(&s, cudaStreamNonBlocking); return s;
    }();
    static cudaEvent_t evRoot = []() {
        cudaEvent_t e; cudaEventCreateWithFlags(&e, cudaEventDisableTiming); return e;
    }();
    static cudaEvent_t evW = []() {
        cudaEvent_t e; cudaEventCreateWithFlags(&e, cudaEventDisableTiming); return e;
    }();
    static cudaEvent_t evQK = []() {
        cudaEvent_t e; cudaEventCreateWithFlags(&e, cudaEventDisableTiming); return e;
    }();
    static cudaEvent_t evB = []() {
        cudaEvent_t e; cudaEventCreateWithFlags(&e, cudaEventDisableTiming); return e;
    }();

    const int nTok = NTOK * DD;   // 8.4M
    const int nW   = DD * DD;     // 4.2M
    dim3 gQK(DD / 128, NTOK / 128, 2);   // (16, 32, 2)
    dim3 gG(DD / 128, NTOK / 128);
    dim3 gZ(8, BB * HH);
    dim3 gScan(BB * HH, NCH);
    dim3 gW3(nW / 1024, 3);

    // fork s2
    cudaEventRecord(evRoot, 0);
    cudaStreamWaitEvent(s2, evRoot, 0);

    // s2: weight conversions (QKV batched, then O)
    tofp16x3_kernel<<<gW3, 256, 0, s2>>>(wq, wqh, wk, wkh, wv, wvh, nW);
    cudaEventRecord(evW, s2);
    tofp16_kernel<<<nW / 1024, 256, 0, s2>>>(wo, woh, nW);

    // s0: x conversion, then batched QK GEMM
    tofp16_kernel<<<nTok / 1024, 256>>>(x, xh, nTok);
    cudaStreamWaitEvent(0, evW, 0);
    gemm_qk<<<gQK, 128, GSM2>>>(xh, wqh, wkh, bq, bk, qh, kh);
    cudaEventRecord(evQK, 0);

    // s2: V GEMM + scan prep, CONCURRENT with z_mma on s0
    cudaStreamWaitEvent(s2, evQK, 0);
    gemm_h<<<gG, 128, GSM2, s2>>>(xh, wvh, bv, vh);
    vchunk_kernel<<<gScan, HDIM, 0, s2>>>(vh);
    vprefix_kernel<<<BB * HH, HDIM, 0, s2>>>();
    cudaEventRecord(evB, s2);

    // s0: z (overlaps V chain)
    z_mma<<<gZ, 256, ZSMEM>>>(qh, kh);

    // join: scan_apply needs z (s0) + vprefix & woh (s2)
    cudaStreamWaitEvent(0, evB, 0);
    scan_apply_kernel<<<gScan, HDIM>>>(vh, ah);
    gemm_o<<<gG, 128, GSM2>>>(ah, woh, bo, out);
}

// round 16
// speedup vs baseline: 1.0635x; 1.0635x over previous
#include <cuda_runtime.h>
#include <cuda_fp16.h>
#include <math.h>
#include <stdint.h>

// ---------------------------------------------------------------------------
// MultiHeadSelfAttention, B=2, S=2048, D=2048, H=16, HD=128
//
//   attn_i = ( sum_{j<i} v_j + exp(s_ii) * v_i ) / Z_i
//   Z_i    = i + sum_{r>=i} exp( (q_i . k_r) / sqrt(D) )
//
// Round 15: GEMM concurrency fix. ncu showed tensor=47%, occ=12% ->
// latency-bound at 8 warps/SM. New core: 256 threads, 8 warps (2x4),
// warp tile 64x32, acc 64 regs -> 2 CTAs/SM = 16 warps/SM.
// Schedule reverted to R14 (batched QKV; z serial after).
// ---------------------------------------------------------------------------

#define BB 2
#define SS 2048
#define DD 2048
#define HH 16
#define HDIM 128
#define NTOK (BB * SS)         // 4096
#define NCH 16
#define RS2 144                // gemm smem row stride (128B data + 16B pad)
#define STG (128 * RS2)        // one tile = 18432 B
#define GSM2 (4 * STG)         // 2 stages x (A + B) = 73728 B
#define ZRS 272                // z smem row stride (256B data + 16B pad)

// fp32 scratch
__device__ float g_Z[BB * HH * SS];
__device__ float g_E[BB * HH * SS];
__device__ float g_cs[BB * HH * NCH * HDIM];

// fp16 scratch
__device__ __half g_xh[(size_t)NTOK * DD];
__device__ __half g_qh[(size_t)NTOK * DD];
__device__ __half g_kh[(size_t)NTOK * DD];
__device__ __half g_vh[(size_t)NTOK * DD];
__device__ __half g_ah[(size_t)NTOK * DD];
__device__ __half g_wqh[(size_t)DD * DD];
__device__ __half g_wkh[(size_t)DD * DD];
__device__ __half g_wvh[(size_t)DD * DD];
__device__ __half g_woh[(size_t)DD * DD];

// ---------------------------------------------------------------------------
// Helpers (base compute_103 ISA only)
// ---------------------------------------------------------------------------
__device__ __forceinline__ uint32_t smem_u32(const void* p) {
    return (uint32_t)__cvta_generic_to_shared(p);
}

__device__ __forceinline__ void cp16(uint32_t dst, const void* src) {
    asm volatile("cp.async.cg.shared.global [%0], [%1], 16;" :: "r"(dst), "l"(src));
}

__device__ __forceinline__ void ldsm4(uint32_t& r0, uint32_t& r1, uint32_t& r2,
                                      uint32_t& r3, uint32_t addr) {
    asm volatile("ldmatrix.sync.aligned.m8n8.x4.shared.b16 {%0,%1,%2,%3}, [%4];"
                 : "=r"(r0), "=r"(r1), "=r"(r2), "=r"(r3) : "r"(addr));
}

__device__ __forceinline__ void mma_f16(float* c, const uint32_t* a,
                                        uint32_t b0, uint32_t b1) {
    asm volatile("mma.sync.aligned.m16n8k16.row.col.f32.f16.f16.f32 "
                 "{%0,%1,%2,%3}, {%4,%5,%6,%7}, {%8,%9}, {%0,%1,%2,%3};"
                 : "+f"(c[0]), "+f"(c[1]), "+f"(c[2]), "+f"(c[3])
                 : "r"(a[0]), "r"(a[1]), "r"(a[2]), "r"(a[3]), "r"(b0), "r"(b1));
}

// ---------------------------------------------------------------------------
// fp32 -> fp16 conversions
// ---------------------------------------------------------------------------
__global__ __launch_bounds__(256) void tofp16_kernel(
    const float* __restrict__ in, __half* __restrict__ out, int n)
{
    int i = (blockIdx.x * 256 + threadIdx.x) * 4;
    if (i >= n) return;
    float4 v = *(const float4*)(in + i);
    __half2* op = reinterpret_cast<__half2*>(out + i);
    op[0] = __floats2half2_rn(v.x, v.y);
    op[1] = __floats2half2_rn(v.z, v.w);
}

__global__ __launch_bounds__(256) void tofp16x3_kernel(
    const float* __restrict__ in0, __half* __restrict__ out0,
    const float* __restrict__ in1, __half* __restrict__ out1,
    const float* __restrict__ in2, __half* __restrict__ out2, int n)
{
    const float* in = (blockIdx.y == 0) ? in0 : (blockIdx.y == 1) ? in1 : in2;
    __half* out     = (blockIdx.y == 0) ? out0 : (blockIdx.y == 1) ? out1 : out2;
    int i = (blockIdx.x * 256 + threadIdx.x) * 4;
    if (i >= n) return;
    float4 v = *(const float4*)(in + i);
    __half2* op = reinterpret_cast<__half2*>(out + i);
    op[0] = __floats2half2_rn(v.x, v.y);
    op[1] = __floats2half2_rn(v.z, v.w);
}

// ---------------------------------------------------------------------------
// GEMM core: acc += A[128xK] * B[128xK]^T over 32 BK=64 chunks.
// 256 threads, 8 warps (2x4), warp tile 64x32 -> acc[4][4][4] (64 regs).
// Double-buffered cp.async; rows padded to 144B (conflict-free ldsm).
// ---------------------------------------------------------------------------
__device__ __forceinline__ void gemm_load_chunk(
    const __half* __restrict__ A, const __half* __restrict__ B,
    int bm, int bn, int k0, unsigned char* sA, unsigned char* sB, int tid)
{
#pragma unroll
    for (int l = 0; l < 4; l++) {
        int i = tid + l * 256;          // 1024 x 16B per tile
        int r = i >> 3;
        int seg = i & 7;
        cp16(smem_u32(sA + r * RS2 + seg * 16),
             A + (size_t)(bm + r) * DD + k0 + seg * 8);
        cp16(smem_u32(sB + r * RS2 + seg * 16),
             B + (size_t)(bn + r) * DD + k0 + seg * 8);
    }
    asm volatile("cp.async.commit_group;" ::: "memory");
}

__device__ __forceinline__ void gemm_core(
    const __half* __restrict__ A, const __half* __restrict__ B,
    int bm, int bn, int tid, unsigned char* gsm, float acc[4][4][4])
{
    unsigned char* sA[2] = { gsm, gsm + 2 * STG };
    unsigned char* sB[2] = { gsm + STG, gsm + 3 * STG };
    const int lid = tid & 31;
    const int wid = tid >> 5;
    const int wm = wid >> 2;          // 0..1 -> 64 rows
    const int wn = wid & 3;           // 0..3 -> 32 cols
    const int nch = 32;

    const int rowsel = (lid & 7) + ((lid >> 3) & 1) * 8;
    const int kbsel = (lid >> 4) * 16;

    gemm_load_chunk(A, B, bm, bn, 0, sA[0], sB[0], tid);

    for (int c = 0; c < nch; c++) {
        if (c + 1 < nch) {
            gemm_load_chunk(A, B, bm, bn, (c + 1) << 6,
                            sA[(c + 1) & 1], sB[(c + 1) & 1], tid);
            asm volatile("cp.async.wait_group 1;" ::: "memory");
        } else {
            asm volatile("cp.async.wait_group 0;" ::: "memory");
        }
        __syncthreads();

        const int buf = c & 1;
        uint32_t aBase = smem_u32(sA[buf]) + (wm * 64 + rowsel) * RS2 + kbsel;
        uint32_t bBase = smem_u32(sB[buf]) + (wn * 32 + rowsel) * RS2 + kbsel;

#pragma unroll
        for (int ks = 0; ks < 4; ks++) {
            uint32_t a[4][4];
#pragma unroll
            for (int mf = 0; mf < 4; mf++)
                ldsm4(a[mf][0], a[mf][1], a[mf][2], a[mf][3],
                      aBase + mf * 16 * RS2 + ks * 32);
#pragma unroll
            for (int ng = 0; ng < 2; ng++) {
                uint32_t r0, r1, r2, r3;
                ldsm4(r0, r1, r2, r3, bBase + ng * 16 * RS2 + ks * 32);
#pragma unroll
                for (int mf = 0; mf < 4; mf++) {
                    mma_f16(acc[mf][2 * ng + 0], a[mf], r0, r2);
                    mma_f16(acc[mf][2 * ng + 1], a[mf], r1, r3);
                }
            }
        }
        __syncthreads();
    }
}

// Batched QKV: grid.z selects weight/bias/fp16 output.
__global__ __launch_bounds__(256, 2) void gemm_qkv(
    const __half* __restrict__ A,
    const __half* __restrict__ Bq, const __half* __restrict__ Bk,
    const __half* __restrict__ Bv,
    const float* __restrict__ biasq, const float* __restrict__ biask,
    const float* __restrict__ biasv,
    __half* __restrict__ Cq, __half* __restrict__ Ck, __half* __restrict__ Cv)
{
    extern __shared__ __align__(16) unsigned char gsm[];
    const int z = blockIdx.z;
    const __half* B = (z == 0) ? Bq : (z == 1) ? Bk : Bv;
    const float* bias = (z == 0) ? biasq : (z == 1) ? biask : biasv;
    __half* Ch = (z == 0) ? Cq : (z == 1) ? Ck : Cv;

    const int tid = threadIdx.x;
    const int lid = tid & 31;
    const int wid = tid >> 5;
    const int wm = wid >> 2, wn = wid & 3;
    const int bn = blockIdx.x * 128;
    const int bm = blockIdx.y * 128;

    float acc[4][4][4];
#pragma unroll
    for (int i = 0; i < 4; i++)
#pragma unroll
        for (int j = 0; j < 4; j++)
#pragma unroll
            for (int q = 0; q < 4; q++) acc[i][j][q] = 0.0f;

    gemm_core(A, B, bm, bn, tid, gsm, acc);

    const int trow = lid >> 2;
    const int tcol = (lid & 3) * 2;
#pragma unroll
    for (int mf = 0; mf < 4; mf++) {
        int r0 = bm + wm * 64 + mf * 16 + trow;
#pragma unroll
        for (int nt = 0; nt < 4; nt++) {
            int cc = bn + wn * 32 + nt * 8 + tcol;
            float2 bv = *(const float2*)(bias + cc);
            *(__half2*)(Ch + (size_t)r0 * DD + cc) =
                __floats2half2_rn(acc[mf][nt][0] + bv.x, acc[mf][nt][1] + bv.y);
            *(__half2*)(Ch + (size_t)(r0 + 8) * DD + cc) =
                __floats2half2_rn(acc[mf][nt][2] + bv.x, acc[mf][nt][3] + bv.y);
        }
    }
}

// O projection: fp32 output.
__global__ __launch_bounds__(256, 2) void gemm_o(
    const __half* __restrict__ A, const __half* __restrict__ B,
    const float* __restrict__ bias, float* __restrict__ C)
{
    extern __shared__ __align__(16) unsigned char gsm[];
    const int tid = threadIdx.x;
    const int lid = tid & 31;
    const int wid = tid >> 5;
    const int wm = wid >> 2, wn = wid & 3;
    const int bn = blockIdx.x * 128;
    const int bm = blockIdx.y * 128;

    float acc[4][4][4];
#pragma unroll
    for (int i = 0; i < 4; i++)
#pragma unroll
        for (int j = 0; j < 4; j++)
#pragma unroll
            for (int q = 0; q < 4; q++) acc[i][j][q] = 0.0f;

    gemm_core(A, B, bm, bn, tid, gsm, acc);

    const int trow = lid >> 2;
    const int tcol = (lid & 3) * 2;
#pragma unroll
    for (int mf = 0; mf < 4; mf++) {
        int r0 = bm + wm * 64 + mf * 16 + trow;
#pragma unroll
        for (int nt = 0; nt < 4; nt++) {
            int cc = bn + wn * 32 + nt * 8 + tcol;
            float2 bv = *(const float2*)(bias + cc);
            *(float2*)(C + (size_t)r0 * DD + cc) =
                make_float2(acc[mf][nt][0] + bv.x, acc[mf][nt][1] + bv.y);
            *(float2*)(C + (size_t)(r0 + 8) * DD + cc) =
                make_float2(acc[mf][nt][2] + bv.x, acc[mf][nt][3] + bv.y);
        }
    }
}

// ---------------------------------------------------------------------------
// z_mma: fp16 HMMA Z row-sums, reflected-pair balanced.
// Grid: (8, BB*HH). CTA bx handles i-tiles bx and 15-bx => uniform 34 chunks.
// ---------------------------------------------------------------------------
#define ZSMEM (128 * ZRS + 2 * 64 * ZRS)   // 69632

__global__ __launch_bounds__(256) void z_mma(
    const __half* __restrict__ Qh, const __half* __restrict__ Kh)
{
    extern __shared__ __align__(16) unsigned char zsm[];
    unsigned char* Qs = zsm;                    // 128 x 272B
    unsigned char* Ks[2] = { zsm + 128 * ZRS, zsm + 128 * ZRS + 64 * ZRS };

    const int tid = threadIdx.x;
    const int lid = tid & 31;
    const int w = tid >> 5;
    const int bh = blockIdx.y;
    const int b = bh >> 4;
    const int h = bh & 15;
    const float scale = 0.022097086912079612f;   // 1/sqrt(2048)

    const __half* Kg = Kh + (size_t)b * SS * DD + h * HDIM;
    float* Ep = g_E + (size_t)bh * SS;

    const int rowsel = (lid & 7) + ((lid >> 3) & 1) * 8;
    const int kbsel = (lid >> 4) * 16;

#pragma unroll 1
    for (int half = 0; half < 2; half++) {
        const int tile = (half == 0) ? (int)blockIdx.x : (15 - (int)blockIdx.x);
        const int i0 = tile * 128;
        const __half* Qg = Qh + ((size_t)b * SS + i0) * DD + h * HDIM;

        for (int i = tid; i < 128 * 16; i += 256) {
            int r = i >> 4, seg = i & 15;
            cp16(smem_u32(Qs + r * ZRS + seg * 16), Qg + (size_t)r * DD + seg * 8);
        }
        asm volatile("cp.async.commit_group;" ::: "memory");

        for (int i = tid; i < 64 * 16; i += 256) {
            int r = i >> 4, seg = i & 15;
            cp16(smem_u32(Ks[0] + r * ZRS + seg * 16),
                 Kg + (size_t)(i0 + r) * DD + seg * 8);
        }
        asm volatile("cp.async.commit_group;" ::: "memory");
        asm volatile("cp.async.wait_group 0;" ::: "memory");
        __syncthreads();

        uint32_t afr[8][4];
        {
            uint32_t aAddr = smem_u32(Qs) + (w * 16 + rowsel) * ZRS + kbsel;
#pragma unroll
            for (int ks = 0; ks < 8; ks++)
                ldsm4(afr[ks][0], afr[ks][1], afr[ks][2], afr[ks][3],
                      aAddr + ks * 32);
        }

        const int gi0 = i0 + w * 16 + (lid >> 2);    // rows gi0 and gi0+8
        float z0 = 0.0f, z1 = 0.0f;

        const int nch = (SS - i0) >> 6;
        for (int c = 0; c < nch; c++) {
            if (c + 1 < nch) {
                int r1 = i0 + (c + 1) * 64;
                unsigned char* kb = Ks[(c + 1) & 1];
                for (int i = tid; i < 64 * 16; i += 256) {
                    int r = i >> 4, seg = i & 15;
                    cp16(smem_u32(kb + r * ZRS + seg * 16),
                         Kg + (size_t)(r1 + r) * DD + seg * 8);
                }
                asm volatile("cp.async.commit_group;" ::: "memory");
                asm volatile("cp.async.wait_group 1;" ::: "memory");
            } else {
                asm volatile("cp.async.wait_group 0;" ::: "memory");
            }
            __syncthreads();

            const int r0 = i0 + c * 64;
            if (r0 + 64 > i0 + w * 16) {
                float sacc[8][4];
#pragma unroll
                for (int nt = 0; nt < 8; nt++)
#pragma unroll
                    for (int q = 0; q < 4; q++) sacc[nt][q] = 0.0f;

                uint32_t bAddr = smem_u32(Ks[c & 1]) + rowsel * ZRS + kbsel;
#pragma unroll
                for (int ks = 0; ks < 8; ks++) {
#pragma unroll
                    for (int ng = 0; ng < 4; ng++) {
                        uint32_t r0r, r1r, r2r, r3r;
                        ldsm4(r0r, r1r, r2r, r3r, bAddr + ng * 16 * ZRS + ks * 32);
                        mma_f16(sacc[2 * ng + 0], afr[ks], r0r, r2r);
                        mma_f16(sacc[2 * ng + 1], afr[ks], r1r, r3r);
                    }
                }

                const bool needmask = (r0 < i0 + w * 16 + 16);
                const int grb = r0 + 2 * (lid & 3);
#pragma unroll
                for (int nt = 0; nt < 8; nt++) {
                    int gr = grb + nt * 8;
                    if (!needmask) {
                        z0 += __expf(sacc[nt][0] * scale) + __expf(sacc[nt][1] * scale);
                        z1 += __expf(sacc[nt][2] * scale) + __expf(sacc[nt][3] * scale);
                    } else {
                        if (gr >= gi0) {
                            float e = __expf(sacc[nt][0] * scale);
                            z0 += e;
                            if (gr == gi0) Ep[gi0] = e;
                        }
                        if (gr + 1 >= gi0) {
                            float e = __expf(sacc[nt][1] * scale);
                            z0 += e;
                            if (gr + 1 == gi0) Ep[gi0] = e;
                        }
                        if (gr >= gi0 + 8) {
                            float e = __expf(sacc[nt][2] * scale);
                            z1 += e;
                            if (gr == gi0 + 8) Ep[gi0 + 8] = e;
                        }
                        if (gr + 1 >= gi0 + 8) {
                            float e = __expf(sacc[nt][3] * scale);
                            z1 += e;
                            if (gr + 1 == gi0 + 8) Ep[gi0 + 8] = e;
                        }
                    }
                }
            }
            __syncthreads();
        }

        z0 += __shfl_xor_sync(0xffffffffu, z0, 1);
        z0 += __shfl_xor_sync(0xffffffffu, z0, 2);
        z1 += __shfl_xor_sync(0xffffffffu, z1, 1);
        z1 += __shfl_xor_sync(0xffffffffu, z1, 2);
        if ((lid & 3) == 0) {
            g_Z[(size_t)bh * SS + gi0] = (float)gi0 + z0;
            g_Z[(size_t)bh * SS + gi0 + 8] = (float)(gi0 + 8) + z1;
        }
        __syncthreads();   // smem reuse across tiles
    }
}

// ---------------------------------------------------------------------------
// Prefix-sum of V (fp16) + apply -> fp16 attn
// ---------------------------------------------------------------------------
__global__ void vchunk_kernel(const __half* __restrict__ V)
{
    const int bh = blockIdx.x, ch = blockIdx.y, d = threadIdx.x;
    const int b = bh >> 4, h = bh & 15;
    const __half* vp = V + ((size_t)b * SS + ch * 128) * DD + h * HDIM + d;
    float sum = 0.0f;
#pragma unroll 8
    for (int i = 0; i < 128; i++) sum += __half2float(vp[(size_t)i * DD]);
    g_cs[((size_t)bh * NCH + ch) * HDIM + d] = sum;
}

__global__ void vprefix_kernel()
{
    const int bh = blockIdx.x, d = threadIdx.x;
    float run = 0.0f;
    for (int ch = 0; ch < NCH; ch++) {
        size_t idx = ((size_t)bh * NCH + ch) * HDIM + d;
        float t = g_cs[idx];
        g_cs[idx] = run;
        run += t;
    }
}

__global__ void scan_apply_kernel(const __half* __restrict__ V,
                                  __half* __restrict__ Ah)
{
    const int bh = blockIdx.x, ch = blockIdx.y, d = threadIdx.x;
    const int b = bh >> 4, h = bh & 15;
    float run = g_cs[((size_t)bh * NCH + ch) * HDIM + d];
    const size_t base = ((size_t)b * SS + ch * 128) * DD + h * HDIM + d;
    const __half* vp = V + base;
    const float* Ep = g_E + (size_t)bh * SS + ch * 128;
    const float* Zp = g_Z + (size_t)bh * SS + ch * 128;
#pragma unroll 4
    for (int i = 0; i < 128; i++) {
        float vv = __half2float(vp[(size_t)i * DD]);
        float rcp = __fdividef(1.0f, Zp[i]);
        Ah[base + (size_t)i * DD] = __float2half_rn((run + Ep[i] * vv) * rcp);
        run += vv;
    }
}

// ---------------------------------------------------------------------------
// Launch: R14 schedule (batched QKV) with the new high-occupancy GEMM core
// ---------------------------------------------------------------------------
extern "C" void kernel_launch(void* const* d_in, const int* in_sizes, int n_in,
                              void* d_out, int out_size)
{
    const float* x   = (const float*)d_in[0];
    const float* wq  = (const float*)d_in[1];
    const float* bq  = (const float*)d_in[2];
    const float* wk  = (const float*)d_in[3];
    const float* bk  = (const float*)d_in[4];
    const float* wv  = (const float*)d_in[5];
    const float* bv  = (const float*)d_in[6];
    const float* wo  = (const float*)d_in[7];
    const float* bo  = (const float*)d_in[8];
    float* out = (float*)d_out;

    void *pqh, *pkh, *pvh, *pxh, *pah, *pwqh, *pwkh, *pwvh, *pwoh;
    cudaGetSymbolAddress(&pqh, g_qh);
    cudaGetSymbolAddress(&pkh, g_kh);
    cudaGetSymbolAddress(&pvh, g_vh);
    cudaGetSymbolAddress(&pxh, g_xh);
    cudaGetSymbolAddress(&pah, g_ah);
    cudaGetSymbolAddress(&pwqh, g_wqh);
    cudaGetSymbolAddress(&pwkh, g_wkh);
    cudaGetSymbolAddress(&pwvh, g_wvh);
    cudaGetSymbolAddress(&pwoh, g_woh);

    __half* qh = (__half*)pqh;
    __half* kh = (__half*)pkh;
    __half* vh = (__half*)pvh;
    __half* xh = (__half*)pxh;
    __half* ah = (__half*)pah;
    __half* wqh = (__half*)pwqh;
    __half* wkh = (__half*)pwkh;
    __half* wvh = (__half*)pwvh;
    __half* woh = (__half*)pwoh;

    cudaFuncSetAttribute(gemm_qkv, cudaFuncAttributeMaxDynamicSharedMemorySize, GSM2);
    cudaFuncSetAttribute(gemm_o, cudaFuncAttributeMaxDynamicSharedMemorySize, GSM2);
    cudaFuncSetAttribute(z_mma, cudaFuncAttributeMaxDynamicSharedMemorySize, ZSMEM);

    static cudaStream_t s2 = []() {
        cudaStream_t s; cudaStreamCreateWithFlags(&s, cudaStreamNonBlocking); return s;
    }();
    static cudaEvent_t evRoot = []() {
        cudaEvent_t e; cudaEventCreateWithFlags(&e, cudaEventDisableTiming); return e;
    }();
    static cudaEvent_t evW = []() {
        cudaEvent_t e; cudaEventCreateWithFlags(&e, cudaEventDisableTiming); return e;
    }();
    static cudaEvent_t evQKV = []() {
        cudaEvent_t e; cudaEventCreateWithFlags(&e, cudaEventDisableTiming); return e;
    }();
    static cudaEvent_t evB = []() {
        cudaEvent_t e; cudaEventCreateWithFlags(&e, cudaEventDisableTiming); return e;
    }();

    const int nTok = NTOK * DD;   // 8.4M
    const int nW   = DD * DD;     // 4.2M
    dim3 gQKV(DD / 128, NTOK / 128, 3);   // (16, 32, 3)
    dim3 gG(DD / 128, NTOK / 128);
    dim3 gZ(8, BB * HH);
    dim3 gScan(BB * HH, NCH);
    dim3 gW3(nW / 1024, 3);

    // fork s2
    cudaEventRecord(evRoot, 0);
    cudaStreamWaitEvent(s2, evRoot, 0);

    // s2: weight conversions (QKV batched, then O)
    tofp16x3_kernel<<<gW3, 256, 0, s2>>>(wq, wqh, wk, wkh, wv, wvh, nW);
    cudaEventRecord(evW, s2);
    tofp16_kernel<<<nW / 1024, 256, 0, s2>>>(wo, woh, nW);

    // s0: x conversion, then batched QKV GEMM
    tofp16_kernel<<<nTok / 1024, 256>>>(x, xh, nTok);
    cudaStreamWaitEvent(0, evW, 0);
    gemm_qkv<<<gQKV, 256, GSM2>>>(xh, wqh, wkh, wvh, bq, bk, bv, qh, kh, vh);
    cudaEventRecord(evQKV, 0);

    // s2: scan prep once V is ready
    cudaStreamWaitEvent(s2, evQKV, 0);
    vchunk_kernel<<<gScan, HDIM, 0, s2>>>(vh);
    vprefix_kernel<<<BB * HH, HDIM, 0, s2>>>();
    cudaEventRecord(evB, s2);

    // s0: z
    z_mma<<<gZ, 256, ZSMEM>>>(qh, kh);

    // join: scan_apply needs z (s0) + vprefix & woh (s2)
    cudaStreamWaitEvent(0, evB, 0);
    scan_apply_kernel<<<gScan, HDIM>>>(vh, ah);
    gemm_o<<<gG, 256, GSM2>>>(ah, woh, bo, out);
}